// round 14
// baseline (speedup 1.0000x reference)
#include <cuda_runtime.h>
#include <cuda_bf16.h>
#include <math.h>
#include <stdint.h>

#define B_    32
#define T_    512
#define HID_  1024
#define G4    4096
#define NREC  128

typedef unsigned int u32;
typedef unsigned long long ull;
typedef unsigned short u16;

// ===========================================================================
// Device scratch
// ===========================================================================
__device__ float g_xg[(size_t)B_ * T_ * G4];          // [B][T][4H] fp32
__device__ __align__(16) u16 g_hhi[B_ * HID_];        // h bf16 hi, [b][j]
__device__ __align__(16) u16 g_hlo[B_ * HID_];        // h bf16 lo, [b][j]
__device__ u32 g_bar_cnt, g_bar_gen;

// ===========================================================================
// helpers
// ===========================================================================
__device__ __forceinline__ u32 smem_u32(const void* p) {
    u32 a;
    asm("{ .reg .u64 t; cvta.to.shared.u64 t, %1; cvt.u32.u64 %0, t; }" : "=r"(a) : "l"(p));
    return a;
}
__device__ __forceinline__ void ldsm_x4(u32& r0, u32& r1, u32& r2, u32& r3, u32 addr) {
    asm volatile("ldmatrix.sync.aligned.m8n8.x4.shared.b16 {%0,%1,%2,%3}, [%4];"
                 : "=r"(r0), "=r"(r1), "=r"(r2), "=r"(r3) : "r"(addr));
}
// NON-trans x2: correct for B operand when H is stored [batch][k] (k contiguous)
__device__ __forceinline__ void ldsm_x2(u32& r0, u32& r1, u32 addr) {
    asm volatile("ldmatrix.sync.aligned.m8n8.x2.shared.b16 {%0,%1}, [%2];"
                 : "=r"(r0), "=r"(r1) : "r"(addr));
}
__device__ __forceinline__ void mma_bf16(float& d0, float& d1, float& d2, float& d3,
                                         u32 a0, u32 a1, u32 a2, u32 a3, u32 b0, u32 b1) {
    asm volatile("mma.sync.aligned.m16n8k16.row.col.f32.bf16.bf16.f32 "
                 "{%0,%1,%2,%3}, {%4,%5,%6,%7}, {%8,%9}, {%0,%1,%2,%3};"
                 : "+f"(d0), "+f"(d1), "+f"(d2), "+f"(d3)
                 : "r"(a0), "r"(a1), "r"(a2), "r"(a3), "r"(b0), "r"(b1));
}
// f32x2 (phase-1 GEMM)
__device__ __forceinline__ void ffma2(ull& d, ull a, ull b) {
    asm("fma.rn.f32x2 %0, %1, %2, %0;" : "+l"(d) : "l"(a), "l"(b));
}
__device__ __forceinline__ ull pack2(float x) {
    ull r; asm("mov.b64 %0, {%1, %1};" : "=l"(r) : "r"(__float_as_uint(x))); return r;
}
__device__ __forceinline__ float2 unpack2(ull v) {
    unsigned lo, hi; asm("mov.b64 {%0, %1}, %2;" : "=r"(lo), "=r"(hi) : "l"(v));
    return make_float2(__uint_as_float(lo), __uint_as_float(hi));
}

__device__ __forceinline__ void grid_barrier(unsigned nb) {
    __syncthreads();
    if (threadIdx.x == 0) {
        volatile u32* vgen = &g_bar_gen;
        u32 gen = *vgen;
        __threadfence();
        if (atomicAdd(&g_bar_cnt, 1u) == nb - 1u) {
            g_bar_cnt = 0u;
            __threadfence();
            *vgen = gen + 1u;
        } else {
            while (*vgen == gen) { }
            __threadfence();
        }
    }
    __syncthreads();
}

// ===========================================================================
// Phase 1: xg = x @ W_ih^T + (b_ih + b_hh).  FFMA2 SGEMM (verbatim from R11)
// ===========================================================================
#define BM 128
#define BN 128
#define BK 16
__global__ __launch_bounds__(256) void xg_gemm_kernel(
    const float* __restrict__ x, const float* __restrict__ Wih,
    const float* __restrict__ bih, const float* __restrict__ bhh)
{
    __shared__ __align__(16) float As[BK][BM + 4];
    __shared__ __align__(16) float Bs[BK][BN + 4];
    const int m0 = blockIdx.y * BM, n0 = blockIdx.x * BN;
    const int tid = threadIdx.x;
    const int tx = tid & 15, ty = tid >> 4;
    const int lrow = tid >> 2, lcol = (tid & 3) << 2;

    ull acc[8][4];
    #pragma unroll
    for (int i = 0; i < 8; ++i)
        #pragma unroll
        for (int j = 0; j < 4; ++j) acc[i][j] = 0ull;

    for (int kc = 0; kc < 1024; kc += BK) {
        float4 a0 = *(const float4*)(x   + (size_t)(m0 + lrow)      * 1024 + kc + lcol);
        float4 a1 = *(const float4*)(x   + (size_t)(m0 + lrow + 64) * 1024 + kc + lcol);
        float4 b0 = *(const float4*)(Wih + (size_t)(n0 + lrow)      * 1024 + kc + lcol);
        float4 b1 = *(const float4*)(Wih + (size_t)(n0 + lrow + 64) * 1024 + kc + lcol);
        __syncthreads();
        As[lcol + 0][lrow] = a0.x; As[lcol + 1][lrow] = a0.y;
        As[lcol + 2][lrow] = a0.z; As[lcol + 3][lrow] = a0.w;
        As[lcol + 0][lrow + 64] = a1.x; As[lcol + 1][lrow + 64] = a1.y;
        As[lcol + 2][lrow + 64] = a1.z; As[lcol + 3][lrow + 64] = a1.w;
        Bs[lcol + 0][lrow] = b0.x; Bs[lcol + 1][lrow] = b0.y;
        Bs[lcol + 2][lrow] = b0.z; Bs[lcol + 3][lrow] = b0.w;
        Bs[lcol + 0][lrow + 64] = b1.x; Bs[lcol + 1][lrow + 64] = b1.y;
        Bs[lcol + 2][lrow + 64] = b1.z; Bs[lcol + 3][lrow + 64] = b1.w;
        __syncthreads();
        #pragma unroll
        for (int k = 0; k < BK; ++k) {
            float4 va0 = *(const float4*)&As[k][ty * 8];
            float4 va1 = *(const float4*)&As[k][ty * 8 + 4];
            ulonglong2 vb0 = *(const ulonglong2*)&Bs[k][tx * 8];
            ulonglong2 vb1 = *(const ulonglong2*)&Bs[k][tx * 8 + 4];
            float ar[8] = {va0.x, va0.y, va0.z, va0.w, va1.x, va1.y, va1.z, va1.w};
            #pragma unroll
            for (int i = 0; i < 8; ++i) {
                ull pa = pack2(ar[i]);
                ffma2(acc[i][0], pa, vb0.x);
                ffma2(acc[i][1], pa, vb0.y);
                ffma2(acc[i][2], pa, vb1.x);
                ffma2(acc[i][3], pa, vb1.y);
            }
        }
    }
    float bias[8];
    #pragma unroll
    for (int j = 0; j < 8; ++j) { int n = n0 + tx * 8 + j; bias[j] = bih[n] + bhh[n]; }
    #pragma unroll
    for (int i = 0; i < 8; ++i) {
        float2 c0v = unpack2(acc[i][0]), c1v = unpack2(acc[i][1]);
        float2 c2v = unpack2(acc[i][2]), c3v = unpack2(acc[i][3]);
        size_t o = (size_t)(m0 + ty * 8 + i) * G4 + n0 + tx * 8;
        float4 v0, v1;
        v0.x = c0v.x + bias[0]; v0.y = c0v.y + bias[1];
        v0.z = c1v.x + bias[2]; v0.w = c1v.y + bias[3];
        v1.x = c2v.x + bias[4]; v1.y = c2v.y + bias[5];
        v1.z = c3v.x + bias[6]; v1.w = c3v.y + bias[7];
        *(float4*)(g_xg + o) = v0; *(float4*)(g_xg + o + 4) = v1;
    }
}

// ===========================================================================
// Phase 2: persistent recurrent kernel on mma.sync m16n8k16 bf16 (3-term split)
// 128 CTAs; CTA r owns 8 hidden units j0=8r.. -> 32 gate rows (rr=q*8+jj).
// D[32x32] = Whi@Hhi + Whi@Hlo + Wlo@Hhi, K=1024 in 4 chunks of 256 (dbl-buf).
// ===========================================================================
#define WPADE 1032                    // W row pad, elems (2064B, 516w === 4 mod 32)
#define HPADE 264                     // H row pad, elems (528B, 132w === 4 mod 32)
#define OFF_WHI  0
#define OFF_WLO  (32 * WPADE * 2)                 // 66048
#define OFF_H    (2 * OFF_WLO)                    // 132096
#define HBUF_SZ  (2 * 32 * HPADE * 2)             // hi+lo = 33792 bytes
#define OFF_GSM  (OFF_H + 2 * HBUF_SZ)            // 199680
#define OFF_CSM  (OFF_GSM + 32 * 33 * 4)          // 203904
#define SMEM_REC (OFF_CSM + 8 * 33 * 4)           // 204960

__global__ __launch_bounds__(256, 1) void lstm_rec_kernel(
    const float* __restrict__ Whh, const float* __restrict__ h0,
    const float* __restrict__ c0, float* __restrict__ out)
{
    extern __shared__ __align__(16) char sm[];
    const u32 smb = smem_u32(sm);
    const int tid = threadIdx.x, lane = tid & 31, wid = tid >> 5;
    const int r = blockIdx.x, j0 = r * 8;

    u16* Whi = (u16*)(sm + OFF_WHI);
    u16* Wlo = (u16*)(sm + OFF_WLO);
    float* gsm = (float*)(sm + OFF_GSM);
    float* csm = (float*)(sm + OFF_CSM);

    // ---- one-time: load W_hh slice, fp32 -> bf16 hi/lo ----
    for (int idx = tid; idx < 32 * 1024; idx += 256) {
        int rr = idx >> 10, k = idx & 1023;
        int q = rr >> 3, jj = rr & 7;
        float w = Whh[(size_t)(q * HID_ + j0 + jj) * HID_ + k];
        __nv_bfloat16 hi = __float2bfloat16(w);
        __nv_bfloat16 lo = __float2bfloat16(w - __bfloat162float(hi));
        Whi[rr * WPADE + k] = __bfloat16_as_ushort(hi);
        Wlo[rr * WPADE + k] = __bfloat16_as_ushort(lo);
    }

    // ---- cell state + h0 publish ----
    const int b = tid >> 3, jj = tid & 7;        // cell mapping: (b, jj)
    csm[jj * 33 + b] = c0[(size_t)b * HID_ + j0 + jj];
    {
        float v = h0[(size_t)b * HID_ + j0 + jj];
        __nv_bfloat16 hi = __float2bfloat16(v);
        __nv_bfloat16 lo = __float2bfloat16(v - __bfloat162float(hi));
        g_hhi[b * HID_ + j0 + jj] = __bfloat16_as_ushort(hi);
        g_hlo[b * HID_ + j0 + jj] = __bfloat16_as_ushort(lo);
    }
    grid_barrier(NREC);    // all h0 published before anyone stages

    // ---- MMA warp mapping: warp = (mh, nq) ----
    const int mh = wid & 1, nq = wid >> 1;
    // A (ldmatrix.x4): row = mh*16 + (lane&15), k-half = (lane>>4)*8
    const u32 aRowOff = (u32)((mh * 16 + (lane & 15)) * WPADE + (lane >> 4) * 8) * 2;
    const u32 aHiBase = smb + OFF_WHI + aRowOff;
    const u32 aLoBase = smb + OFF_WLO + aRowOff;
    // B (ldmatrix.x2 non-trans): row(batch) = nq*8 + (lane&7), k-half = ((lane>>3)&1)*8
    const u32 bRowOff = (u32)((nq * 8 + (lane & 7)) * HPADE + ((lane >> 3) & 1) * 8) * 2;
    const u32 bHiBase0 = smb + OFF_H + bRowOff;             // buf0 hi
    const u32 bHiBase1 = bHiBase0 + HBUF_SZ;                // buf1 hi
    // staging mapping: row b_st, 16B chunk li_st + 8*i
    const int b_st = tid >> 3, li_st = tid & 7;
    u16* hsm = (u16*)(sm + OFF_H);

    for (int t = 0; t < T_; ++t) {
        // xg prefetch (4 gates for (b, jj))
        const size_t xb = (((size_t)b * T_ + t) << 12) + j0 + jj;
        float xgi = __ldcg(g_xg + xb);
        float xgf = __ldcg(g_xg + xb + 1024);
        float xgg = __ldcg(g_xg + xb + 2048);
        float xgo = __ldcg(g_xg + xb + 3072);

        // stage chunk 0 -> buf 0
        {
            const u16* sh = g_hhi + b_st * HID_ + li_st * 8;
            const u16* sl = g_hlo + b_st * HID_ + li_st * 8;
            u16* dh = hsm + b_st * HPADE + li_st * 8;
            u16* dl = dh + 32 * HPADE;
            #pragma unroll
            for (int i = 0; i < 4; ++i) {
                *(uint4*)(dh + i * 64) = __ldcg((const uint4*)(sh + i * 64));
                *(uint4*)(dl + i * 64) = __ldcg((const uint4*)(sl + i * 64));
            }
        }

        float A0 = 0.f, A1 = 0.f, A2 = 0.f, A3 = 0.f;   // Whi*Hhi
        float B0 = 0.f, B1 = 0.f, B2 = 0.f, B3 = 0.f;   // Whi*Hlo
        float C0 = 0.f, C1 = 0.f, C2 = 0.f, C3 = 0.f;   // Wlo*Hhi

        #pragma unroll 1
        for (int c = 0; c < 4; ++c) {
            __syncthreads();      // chunk c staged; buffer (c+1)&1 free
            if (c < 3) {
                const int kb = (c + 1) * 256;
                const int buf = (c + 1) & 1;
                const u16* sh = g_hhi + b_st * HID_ + kb + li_st * 8;
                const u16* sl = g_hlo + b_st * HID_ + kb + li_st * 8;
                u16* dh = hsm + buf * (HBUF_SZ / 2) + b_st * HPADE + li_st * 8;
                u16* dl = dh + 32 * HPADE;
                #pragma unroll
                for (int i = 0; i < 4; ++i) {
                    *(uint4*)(dh + i * 64) = __ldcg((const uint4*)(sh + i * 64));
                    *(uint4*)(dl + i * 64) = __ldcg((const uint4*)(sl + i * 64));
                }
            }
            u32 aH = aHiBase + c * 512;          // 256 elems * 2B
            u32 aL = aLoBase + c * 512;
            u32 bH = (c & 1) ? bHiBase1 : bHiBase0;
            u32 bL = bH + 32 * HPADE * 2;
            #pragma unroll
            for (int kt = 0; kt < 16; ++kt) {
                u32 a0, a1, a2, a3, l0, l1, l2, l3, bh0, bh1, bl0, bl1;
                ldsm_x4(a0, a1, a2, a3, aH);
                ldsm_x4(l0, l1, l2, l3, aL);
                ldsm_x2(bh0, bh1, bH);
                ldsm_x2(bl0, bl1, bL);
                mma_bf16(A0, A1, A2, A3, a0, a1, a2, a3, bh0, bh1);
                mma_bf16(B0, B1, B2, B3, a0, a1, a2, a3, bl0, bl1);
                mma_bf16(C0, C1, C2, C3, l0, l1, l2, l3, bh0, bh1);
                aH += 32; aL += 32; bH += 32; bL += 32;
            }
        }

        // D frag -> gsm
        {
            float d0 = A0 + B0 + C0, d1 = A1 + B1 + C1;
            float d2 = A2 + B2 + C2, d3 = A3 + B3 + C3;
            const int row = mh * 16 + (lane >> 2);
            const int col = nq * 8 + (lane & 3) * 2;
            gsm[row * 33 + col]       = d0;
            gsm[row * 33 + col + 1]   = d1;
            gsm[(row + 8) * 33 + col]     = d2;
            gsm[(row + 8) * 33 + col + 1] = d3;
        }
        __syncthreads();

        // cell update: thread (b, jj); gsm row = q*8 + jj
        {
            float pi = gsm[(jj)      * 33 + b] + xgi;
            float pf = gsm[(8  + jj) * 33 + b] + xgf;
            float pg = gsm[(16 + jj) * 33 + b] + xgg;
            float po = gsm[(24 + jj) * 33 + b] + xgo;
            float ig = 1.0f / (1.0f + expf(-pi));
            float fg = 1.0f / (1.0f + expf(-pf));
            float gt = tanhf(pg);
            float og = 1.0f / (1.0f + expf(-po));
            float cn = fmaf(fg, csm[jj * 33 + b], ig * gt);
            csm[jj * 33 + b] = cn;
            float hv = og * tanhf(cn);
            if (t == T_ - 1) {
                out[(size_t)b * HID_ + j0 + jj] = hv;
            } else {
                __nv_bfloat16 hi = __float2bfloat16(hv);
                __nv_bfloat16 lo = __float2bfloat16(hv - __bfloat162float(hi));
                g_hhi[b * HID_ + j0 + jj] = __bfloat16_as_ushort(hi);
                g_hlo[b * HID_ + j0 + jj] = __bfloat16_as_ushort(lo);
            }
        }
        grid_barrier(NREC);
    }
}

// ===========================================================================
// launch (exactly 2 kernels -> ncu -s 5 -c 1 lands on gemm or rec)
// ===========================================================================
extern "C" void kernel_launch(void* const* d_in, const int* in_sizes, int n_in,
                              void* d_out, int out_size) {
    const float* x   = (const float*)d_in[0];
    const float* h0  = (const float*)d_in[1];
    const float* c0  = (const float*)d_in[2];
    const float* Wih = (const float*)d_in[3];
    const float* Whh = (const float*)d_in[4];
    const float* bih = (const float*)d_in[5];
    const float* bhh = (const float*)d_in[6];
    float* out = (float*)d_out;

    cudaFuncSetAttribute(lstm_rec_kernel,
                         cudaFuncAttributeMaxDynamicSharedMemorySize, SMEM_REC);

    dim3 grid(G4 / BN, (B_ * T_) / BM);
    xg_gemm_kernel<<<grid, 256>>>(x, Wih, bih, bhh);

    lstm_rec_kernel<<<NREC, 256, SMEM_REC>>>(Whh, h0, c0, out);
}

// round 15
// speedup vs baseline: 1.4917x; 1.4917x over previous
#include <cuda_runtime.h>
#include <cuda_bf16.h>
#include <math.h>
#include <stdint.h>

#define B_    32
#define T_    512
#define HID_  1024
#define G4    4096
#define NREC  128
#define NT    512          // threads per rec CTA (16 warps)

typedef unsigned int u32;
typedef unsigned long long ull;
typedef unsigned short u16;

// ===========================================================================
// Device scratch
// ===========================================================================
__device__ float g_xg[(size_t)B_ * T_ * G4];          // [B][T][4H] fp32
__device__ __align__(16) u16 g_hhi[B_ * HID_];        // h bf16 hi, [b][j]
__device__ __align__(16) u16 g_hlo[B_ * HID_];        // h bf16 lo, [b][j]
__device__ u32 g_grp_cnt[16 * 32];                    // 16 group counters, 128B apart
__device__ u32 g_root_cnt, g_root_gen;

// ===========================================================================
// helpers
// ===========================================================================
__device__ __forceinline__ u32 smem_u32(const void* p) {
    u32 a;
    asm("{ .reg .u64 t; cvta.to.shared.u64 t, %1; cvt.u32.u64 %0, t; }" : "=r"(a) : "l"(p));
    return a;
}
__device__ __forceinline__ void ldsm_x4(u32& r0, u32& r1, u32& r2, u32& r3, u32 addr) {
    asm volatile("ldmatrix.sync.aligned.m8n8.x4.shared.b16 {%0,%1,%2,%3}, [%4];"
                 : "=r"(r0), "=r"(r1), "=r"(r2), "=r"(r3) : "r"(addr));
}
__device__ __forceinline__ void mma_bf16(float& d0, float& d1, float& d2, float& d3,
                                         u32 a0, u32 a1, u32 a2, u32 a3, u32 b0, u32 b1) {
    asm volatile("mma.sync.aligned.m16n8k16.row.col.f32.bf16.bf16.f32 "
                 "{%0,%1,%2,%3}, {%4,%5,%6,%7}, {%8,%9}, {%0,%1,%2,%3};"
                 : "+f"(d0), "+f"(d1), "+f"(d2), "+f"(d3)
                 : "r"(a0), "r"(a1), "r"(a2), "r"(a3), "r"(b0), "r"(b1));
}
// f32x2 (phase-1 GEMM)
__device__ __forceinline__ void ffma2(ull& d, ull a, ull b) {
    asm("fma.rn.f32x2 %0, %1, %2, %0;" : "+l"(d) : "l"(a), "l"(b));
}
__device__ __forceinline__ ull pack2(float x) {
    ull r; asm("mov.b64 %0, {%1, %1};" : "=l"(r) : "r"(__float_as_uint(x))); return r;
}
__device__ __forceinline__ float2 unpack2(ull v) {
    unsigned lo, hi; asm("mov.b64 {%0, %1}, %2;" : "=r"(lo), "=r"(hi) : "l"(v));
    return make_float2(__uint_as_float(lo), __uint_as_float(hi));
}

// Two-level grid barrier: 16 groups x 8 CTAs, self-resetting (replay-safe).
__device__ __forceinline__ void grid_barrier_tree(int r) {
    __syncthreads();
    if (threadIdx.x == 0) {
        volatile u32* vgen = &g_root_gen;
        u32 gen = *vgen;
        __threadfence();
        u32* gcnt = &g_grp_cnt[(r >> 3) * 32];
        if (atomicAdd(gcnt, 1u) == 7u) {
            *gcnt = 0u;                       // all 8 arrived; safe to reset
            __threadfence();
            if (atomicAdd(&g_root_cnt, 1u) == 15u) {
                g_root_cnt = 0u;
                __threadfence();
                *vgen = gen + 1u;
            } else {
                while (*vgen == gen) { }
            }
        } else {
            while (*vgen == gen) { }
        }
        __threadfence();
    }
    __syncthreads();
}

// ===========================================================================
// Phase 1: xg = x @ W_ih^T + (b_ih + b_hh).  FFMA2 SGEMM (verbatim, proven)
// ===========================================================================
#define BM 128
#define BN 128
#define BK 16
__global__ __launch_bounds__(256) void xg_gemm_kernel(
    const float* __restrict__ x, const float* __restrict__ Wih,
    const float* __restrict__ bih, const float* __restrict__ bhh)
{
    __shared__ __align__(16) float As[BK][BM + 4];
    __shared__ __align__(16) float Bs[BK][BN + 4];
    const int m0 = blockIdx.y * BM, n0 = blockIdx.x * BN;
    const int tid = threadIdx.x;
    const int tx = tid & 15, ty = tid >> 4;
    const int lrow = tid >> 2, lcol = (tid & 3) << 2;

    ull acc[8][4];
    #pragma unroll
    for (int i = 0; i < 8; ++i)
        #pragma unroll
        for (int j = 0; j < 4; ++j) acc[i][j] = 0ull;

    for (int kc = 0; kc < 1024; kc += BK) {
        float4 a0 = *(const float4*)(x   + (size_t)(m0 + lrow)      * 1024 + kc + lcol);
        float4 a1 = *(const float4*)(x   + (size_t)(m0 + lrow + 64) * 1024 + kc + lcol);
        float4 b0 = *(const float4*)(Wih + (size_t)(n0 + lrow)      * 1024 + kc + lcol);
        float4 b1 = *(const float4*)(Wih + (size_t)(n0 + lrow + 64) * 1024 + kc + lcol);
        __syncthreads();
        As[lcol + 0][lrow] = a0.x; As[lcol + 1][lrow] = a0.y;
        As[lcol + 2][lrow] = a0.z; As[lcol + 3][lrow] = a0.w;
        As[lcol + 0][lrow + 64] = a1.x; As[lcol + 1][lrow + 64] = a1.y;
        As[lcol + 2][lrow + 64] = a1.z; As[lcol + 3][lrow + 64] = a1.w;
        Bs[lcol + 0][lrow] = b0.x; Bs[lcol + 1][lrow] = b0.y;
        Bs[lcol + 2][lrow] = b0.z; Bs[lcol + 3][lrow] = b0.w;
        Bs[lcol + 0][lrow + 64] = b1.x; Bs[lcol + 1][lrow + 64] = b1.y;
        Bs[lcol + 2][lrow + 64] = b1.z; Bs[lcol + 3][lrow + 64] = b1.w;
        __syncthreads();
        #pragma unroll
        for (int k = 0; k < BK; ++k) {
            float4 va0 = *(const float4*)&As[k][ty * 8];
            float4 va1 = *(const float4*)&As[k][ty * 8 + 4];
            ulonglong2 vb0 = *(const ulonglong2*)&Bs[k][tx * 8];
            ulonglong2 vb1 = *(const ulonglong2*)&Bs[k][tx * 8 + 4];
            float ar[8] = {va0.x, va0.y, va0.z, va0.w, va1.x, va1.y, va1.z, va1.w};
            #pragma unroll
            for (int i = 0; i < 8; ++i) {
                ull pa = pack2(ar[i]);
                ffma2(acc[i][0], pa, vb0.x);
                ffma2(acc[i][1], pa, vb0.y);
                ffma2(acc[i][2], pa, vb1.x);
                ffma2(acc[i][3], pa, vb1.y);
            }
        }
    }
    float bias[8];
    #pragma unroll
    for (int j = 0; j < 8; ++j) { int n = n0 + tx * 8 + j; bias[j] = bih[n] + bhh[n]; }
    #pragma unroll
    for (int i = 0; i < 8; ++i) {
        float2 c0v = unpack2(acc[i][0]), c1v = unpack2(acc[i][1]);
        float2 c2v = unpack2(acc[i][2]), c3v = unpack2(acc[i][3]);
        size_t o = (size_t)(m0 + ty * 8 + i) * G4 + n0 + tx * 8;
        float4 v0, v1;
        v0.x = c0v.x + bias[0]; v0.y = c0v.y + bias[1];
        v0.z = c1v.x + bias[2]; v0.w = c1v.y + bias[3];
        v1.x = c2v.x + bias[4]; v1.y = c2v.y + bias[5];
        v1.z = c3v.x + bias[6]; v1.w = c3v.y + bias[7];
        *(float4*)(g_xg + o) = v0; *(float4*)(g_xg + o + 4) = v1;
    }
}

// ===========================================================================
// Phase 2: persistent rec kernel, mma.sync bf16 3-term, 512 threads.
// CTA r owns 8 hidden units -> D[32 gate rows x 32 batch], K=1024.
// Warp = (ksc 0..7, mh 0..1): m16 x n32, K-slice 32 per 256-chunk (2 ktiles),
// 4 chunks double-buffered. Partials psm[8] alias chunk buffer 0.
// ===========================================================================
#define WPADE 1032                    // W row pad (2064B, 16 mod 128 -> conflict-free)
#define HPADE 264                     // H row pad (528B,  16 mod 128)
#define OFF_WHI  0
#define OFF_WLO  (32 * WPADE * 2)                 // 66048
#define OFF_H    (2 * 32 * WPADE * 2)             // 132096
#define HBUF_SZ  (2 * 32 * HPADE * 2)             // hi+lo = 33792 B per buffer
#define OFF_PSM  OFF_H                            // psm aliases buffer 0 (exact fit)
#define OFF_CSM  (OFF_H + 2 * HBUF_SZ)            // 199680
#define SMEM_REC (OFF_CSM + 8 * 33 * 4)           // 200736

__global__ __launch_bounds__(NT, 1) void lstm_rec_kernel(
    const float* __restrict__ Whh, const float* __restrict__ h0,
    const float* __restrict__ c0, float* __restrict__ out)
{
    extern __shared__ __align__(16) char sm[];
    const u32 smb = smem_u32(sm);
    const int tid = threadIdx.x, lane = tid & 31, wid = tid >> 5;
    const int r = blockIdx.x, j0 = r * 8;

    u16* Whi = (u16*)(sm + OFF_WHI);
    u16* Wlo = (u16*)(sm + OFF_WLO);
    float* psm = (float*)(sm + OFF_PSM);     // [8][32][33]
    float* csm = (float*)(sm + OFF_CSM);     // [8][33]

    // ---- one-time: W_hh slice -> bf16 hi/lo in SMEM ----
    for (int idx = tid; idx < 32 * 1024; idx += NT) {
        int rr = idx >> 10, k = idx & 1023;
        int q = rr >> 3, jj = rr & 7;
        float w = Whh[(size_t)(q * HID_ + j0 + jj) * HID_ + k];
        __nv_bfloat16 hi = __float2bfloat16(w);
        __nv_bfloat16 lo = __float2bfloat16(w - __bfloat162float(hi));
        Whi[rr * WPADE + k] = __bfloat16_as_ushort(hi);
        Wlo[rr * WPADE + k] = __bfloat16_as_ushort(lo);
    }

    // ---- cell state + h0 publish (threads < 256) ----
    const int b = tid >> 3, jj = tid & 7;
    if (tid < 256) {
        csm[jj * 33 + b] = c0[(size_t)b * HID_ + j0 + jj];
        float v = h0[(size_t)b * HID_ + j0 + jj];
        __nv_bfloat16 hi = __float2bfloat16(v);
        __nv_bfloat16 lo = __float2bfloat16(v - __bfloat162float(hi));
        g_hhi[b * HID_ + j0 + jj] = __bfloat16_as_ushort(hi);
        g_hlo[b * HID_ + j0 + jj] = __bfloat16_as_ushort(lo);
    }
    grid_barrier_tree(r);

    // ---- warp mapping ----
    const int ksc = wid & 7;             // K-slice within chunk: 32 elems
    const int mh  = wid >> 3;            // m-half (16 gate rows)
    // A base (ldmatrix.x4): row = mh*16 + (lane&15), k-half = (lane>>4)*8
    const u32 aOff = (u32)((mh * 16 + (lane & 15)) * WPADE + (lane >> 4) * 8) * 2;
    // B base (x4 non-trans): batch = (lane>>4)*8 + (lane&7), k-seg = ((lane>>3)&1)*8
    const u32 bOff = (u32)(((lane >> 4) * 8 + (lane & 7)) * HPADE + ((lane >> 3) & 1) * 8) * 2;
    // staging: row = tid>>4, 16B seg = tid&15 (+16)
    const int st_row = tid >> 4, st_seg = tid & 15;

    for (int t = 0; t < T_; ++t) {
        // xg prefetch
        float xgi, xgf, xgg, xgo;
        if (tid < 256) {
            const size_t xb = (((size_t)b * T_ + t) << 12) + j0 + jj;
            xgi = __ldcg(g_xg + xb);
            xgf = __ldcg(g_xg + xb + 1024);
            xgg = __ldcg(g_xg + xb + 2048);
            xgo = __ldcg(g_xg + xb + 3072);
        }

        // stage chunk 0 -> buf 0
        {
            const u16* sh = g_hhi + st_row * HID_ + st_seg * 8;
            const u16* sl = g_hlo + st_row * HID_ + st_seg * 8;
            u16* dh = (u16*)(sm + OFF_H) + st_row * HPADE + st_seg * 8;
            u16* dl = dh + 32 * HPADE;
            #pragma unroll
            for (int i = 0; i < 2; ++i) {
                *(uint4*)(dh + i * 128) = __ldcg((const uint4*)(sh + i * 128));
                *(uint4*)(dl + i * 128) = __ldcg((const uint4*)(sl + i * 128));
            }
        }

        float D[4][4];
        #pragma unroll
        for (int n = 0; n < 4; ++n)
            #pragma unroll
            for (int i = 0; i < 4; ++i) D[n][i] = 0.f;

        #pragma unroll 1
        for (int c = 0; c < 4; ++c) {
            __syncthreads();                  // chunk c staged; other buffer free
            if (c < 3) {
                const int kb = (c + 1) * 256;
                const u32 bufo = OFF_H + ((c + 1) & 1) * HBUF_SZ;
                const u16* sh = g_hhi + st_row * HID_ + kb + st_seg * 8;
                const u16* sl = g_hlo + st_row * HID_ + kb + st_seg * 8;
                u16* dh = (u16*)(sm + bufo) + st_row * HPADE + st_seg * 8;
                u16* dl = dh + 32 * HPADE;
                #pragma unroll
                for (int i = 0; i < 2; ++i) {
                    *(uint4*)(dh + i * 128) = __ldcg((const uint4*)(sh + i * 128));
                    *(uint4*)(dl + i * 128) = __ldcg((const uint4*)(sl + i * 128));
                }
            }
            const u32 kbase = (u32)(c * 256 + ksc * 32);
            u32 aH = smb + OFF_WHI + aOff + kbase * 2;
            u32 aL = smb + OFF_WLO + aOff + kbase * 2;
            const u32 bufb = smb + OFF_H + (c & 1) * HBUF_SZ;
            u32 bH = bufb + bOff + (kbase & 255) * 2;      // k offset within chunk
            u32 bL = bH + 32 * HPADE * 2;
            #pragma unroll
            for (int kt = 0; kt < 2; ++kt) {
                u32 a0, a1, a2, a3, l0, l1, l2, l3;
                u32 bh[8], bl[8];
                ldsm_x4(a0, a1, a2, a3, aH);
                ldsm_x4(l0, l1, l2, l3, aL);
                ldsm_x4(bh[0], bh[1], bh[2], bh[3], bH);
                ldsm_x4(bh[4], bh[5], bh[6], bh[7], bH + 16 * HPADE * 2);
                ldsm_x4(bl[0], bl[1], bl[2], bl[3], bL);
                ldsm_x4(bl[4], bl[5], bl[6], bl[7], bL + 16 * HPADE * 2);
                #pragma unroll
                for (int n = 0; n < 4; ++n)
                    mma_bf16(D[n][0], D[n][1], D[n][2], D[n][3],
                             a0, a1, a2, a3, bh[2 * n], bh[2 * n + 1]);
                #pragma unroll
                for (int n = 0; n < 4; ++n)
                    mma_bf16(D[n][0], D[n][1], D[n][2], D[n][3],
                             a0, a1, a2, a3, bl[2 * n], bl[2 * n + 1]);
                #pragma unroll
                for (int n = 0; n < 4; ++n)
                    mma_bf16(D[n][0], D[n][1], D[n][2], D[n][3],
                             l0, l1, l2, l3, bh[2 * n], bh[2 * n + 1]);
                aH += 32; aL += 32; bH += 32; bL += 32;
            }
        }
        __syncthreads();       // all chunk-2 (buf0) reads done before psm overwrite

        // K-partial D -> psm[ksc]
        {
            const int row = mh * 16 + (lane >> 2);
            const int col = (lane & 3) * 2;
            float* pr = psm + (ksc * 32 + row) * 33;
            #pragma unroll
            for (int n = 0; n < 4; ++n) {
                pr[n * 8 + col]            = D[n][0];
                pr[n * 8 + col + 1]        = D[n][1];
                pr[8 * 33 + n * 8 + col]     = D[n][2];
                pr[8 * 33 + n * 8 + col + 1] = D[n][3];
            }
        }
        __syncthreads();

        // cell update (threads < 256): sum 8 K-partials per gate
        if (tid < 256) {
            float gi = 0.f, gf = 0.f, gg = 0.f, go = 0.f;
            #pragma unroll
            for (int s = 0; s < 8; ++s) {
                const float* ps = psm + s * 32 * 33;
                gi += ps[(jj)      * 33 + b];
                gf += ps[(8  + jj) * 33 + b];
                gg += ps[(16 + jj) * 33 + b];
                go += ps[(24 + jj) * 33 + b];
            }
            float pi = gi + xgi, pf = gf + xgf, pg = gg + xgg, po = go + xgo;
            float ig = 1.0f / (1.0f + expf(-pi));
            float fg = 1.0f / (1.0f + expf(-pf));
            float gt = tanhf(pg);
            float og = 1.0f / (1.0f + expf(-po));
            float cn = fmaf(fg, csm[jj * 33 + b], ig * gt);
            csm[jj * 33 + b] = cn;
            float hv = og * tanhf(cn);
            if (t == T_ - 1) {
                out[(size_t)b * HID_ + j0 + jj] = hv;
            } else {
                __nv_bfloat16 hi = __float2bfloat16(hv);
                __nv_bfloat16 lo = __float2bfloat16(hv - __bfloat162float(hi));
                g_hhi[b * HID_ + j0 + jj] = __bfloat16_as_ushort(hi);
                g_hlo[b * HID_ + j0 + jj] = __bfloat16_as_ushort(lo);
            }
        }
        grid_barrier_tree(r);
    }
}

// ===========================================================================
// launch
// ===========================================================================
extern "C" void kernel_launch(void* const* d_in, const int* in_sizes, int n_in,
                              void* d_out, int out_size) {
    const float* x   = (const float*)d_in[0];
    const float* h0  = (const float*)d_in[1];
    const float* c0  = (const float*)d_in[2];
    const float* Wih = (const float*)d_in[3];
    const float* Whh = (const float*)d_in[4];
    const float* bih = (const float*)d_in[5];
    const float* bhh = (const float*)d_in[6];
    float* out = (float*)d_out;

    cudaFuncSetAttribute(lstm_rec_kernel,
                         cudaFuncAttributeMaxDynamicSharedMemorySize, SMEM_REC);

    dim3 grid(G4 / BN, (B_ * T_) / BM);
    xg_gemm_kernel<<<grid, 256>>>(x, Wih, bih, bhh);

    lstm_rec_kernel<<<NREC, NT, SMEM_REC>>>(Whh, h0, c0, out);
}

// round 16
// speedup vs baseline: 1.6868x; 1.1308x over previous
#include <cuda_runtime.h>
#include <cuda_fp16.h>
#include <math.h>
#include <stdint.h>

#define B_    32
#define T_    512
#define HID_  1024
#define G4    4096
#define NREC  128
#define NT    512          // threads per rec CTA (16 warps)

typedef unsigned int u32;
typedef unsigned long long ull;
typedef unsigned short u16;

// ===========================================================================
// Device scratch
// ===========================================================================
__device__ float g_xg[(size_t)B_ * T_ * G4];          // [B][T][4H] fp32
__device__ __align__(16) u16 g_hhi[B_ * HID_];        // h fp16 hi, [b][j]
__device__ __align__(16) u16 g_hlo[B_ * HID_];        // h fp16 lo, [b][j]
__device__ u32 g_grp_cnt[16 * 32];                    // group counters, 128B apart
__device__ u32 g_root_cnt, g_root_gen;

// ===========================================================================
// helpers
// ===========================================================================
__device__ __forceinline__ u32 smem_u32(const void* p) {
    u32 a;
    asm("{ .reg .u64 t; cvta.to.shared.u64 t, %1; cvt.u32.u64 %0, t; }" : "=r"(a) : "l"(p));
    return a;
}
__device__ __forceinline__ void ldsm_x4(u32& r0, u32& r1, u32& r2, u32& r3, u32 addr) {
    asm volatile("ldmatrix.sync.aligned.m8n8.x4.shared.b16 {%0,%1,%2,%3}, [%4];"
                 : "=r"(r0), "=r"(r1), "=r"(r2), "=r"(r3) : "r"(addr));
}
__device__ __forceinline__ void mma_f16(float& d0, float& d1, float& d2, float& d3,
                                        u32 a0, u32 a1, u32 a2, u32 a3, u32 b0, u32 b1) {
    asm volatile("mma.sync.aligned.m16n8k16.row.col.f32.f16.f16.f32 "
                 "{%0,%1,%2,%3}, {%4,%5,%6,%7}, {%8,%9}, {%0,%1,%2,%3};"
                 : "+f"(d0), "+f"(d1), "+f"(d2), "+f"(d3)
                 : "r"(a0), "r"(a1), "r"(a2), "r"(a3), "r"(b0), "r"(b1));
}
// f32x2 (phase-1 GEMM)
__device__ __forceinline__ void ffma2(ull& d, ull a, ull b) {
    asm("fma.rn.f32x2 %0, %1, %2, %0;" : "+l"(d) : "l"(a), "l"(b));
}
__device__ __forceinline__ ull pack2(float x) {
    ull r; asm("mov.b64 %0, {%1, %1};" : "=l"(r) : "r"(__float_as_uint(x))); return r;
}
__device__ __forceinline__ float2 unpack2(ull v) {
    unsigned lo, hi; asm("mov.b64 {%0, %1}, %2;" : "=r"(lo), "=r"(hi) : "l"(v));
    return make_float2(__uint_as_float(lo), __uint_as_float(hi));
}

// Two-level grid barrier: 16 groups x 8 CTAs, self-resetting (replay-safe).
__device__ __forceinline__ void grid_barrier_tree(int r) {
    __syncthreads();
    if (threadIdx.x == 0) {
        volatile u32* vgen = &g_root_gen;
        u32 gen = *vgen;
        __threadfence();
        u32* gcnt = &g_grp_cnt[(r >> 3) * 32];
        if (atomicAdd(gcnt, 1u) == 7u) {
            *gcnt = 0u;
            __threadfence();
            if (atomicAdd(&g_root_cnt, 1u) == 15u) {
                g_root_cnt = 0u;
                __threadfence();
                *vgen = gen + 1u;
            } else {
                while (*vgen == gen) { }
            }
        } else {
            while (*vgen == gen) { }
        }
        __threadfence();
    }
    __syncthreads();
}

// ===========================================================================
// Phase 1: xg = x @ W_ih^T + (b_ih + b_hh).  FFMA2 SGEMM (verbatim, proven)
// ===========================================================================
#define BM 128
#define BN 128
#define BK 16
__global__ __launch_bounds__(256) void xg_gemm_kernel(
    const float* __restrict__ x, const float* __restrict__ Wih,
    const float* __restrict__ bih, const float* __restrict__ bhh)
{
    __shared__ __align__(16) float As[BK][BM + 4];
    __shared__ __align__(16) float Bs[BK][BN + 4];
    const int m0 = blockIdx.y * BM, n0 = blockIdx.x * BN;
    const int tid = threadIdx.x;
    const int tx = tid & 15, ty = tid >> 4;
    const int lrow = tid >> 2, lcol = (tid & 3) << 2;

    ull acc[8][4];
    #pragma unroll
    for (int i = 0; i < 8; ++i)
        #pragma unroll
        for (int j = 0; j < 4; ++j) acc[i][j] = 0ull;

    for (int kc = 0; kc < 1024; kc += BK) {
        float4 a0 = *(const float4*)(x   + (size_t)(m0 + lrow)      * 1024 + kc + lcol);
        float4 a1 = *(const float4*)(x   + (size_t)(m0 + lrow + 64) * 1024 + kc + lcol);
        float4 b0 = *(const float4*)(Wih + (size_t)(n0 + lrow)      * 1024 + kc + lcol);
        float4 b1 = *(const float4*)(Wih + (size_t)(n0 + lrow + 64) * 1024 + kc + lcol);
        __syncthreads();
        As[lcol + 0][lrow] = a0.x; As[lcol + 1][lrow] = a0.y;
        As[lcol + 2][lrow] = a0.z; As[lcol + 3][lrow] = a0.w;
        As[lcol + 0][lrow + 64] = a1.x; As[lcol + 1][lrow + 64] = a1.y;
        As[lcol + 2][lrow + 64] = a1.z; As[lcol + 3][lrow + 64] = a1.w;
        Bs[lcol + 0][lrow] = b0.x; Bs[lcol + 1][lrow] = b0.y;
        Bs[lcol + 2][lrow] = b0.z; Bs[lcol + 3][lrow] = b0.w;
        Bs[lcol + 0][lrow + 64] = b1.x; Bs[lcol + 1][lrow + 64] = b1.y;
        Bs[lcol + 2][lrow + 64] = b1.z; Bs[lcol + 3][lrow + 64] = b1.w;
        __syncthreads();
        #pragma unroll
        for (int k = 0; k < BK; ++k) {
            float4 va0 = *(const float4*)&As[k][ty * 8];
            float4 va1 = *(const float4*)&As[k][ty * 8 + 4];
            ulonglong2 vb0 = *(const ulonglong2*)&Bs[k][tx * 8];
            ulonglong2 vb1 = *(const ulonglong2*)&Bs[k][tx * 8 + 4];
            float ar[8] = {va0.x, va0.y, va0.z, va0.w, va1.x, va1.y, va1.z, va1.w};
            #pragma unroll
            for (int i = 0; i < 8; ++i) {
                ull pa = pack2(ar[i]);
                ffma2(acc[i][0], pa, vb0.x);
                ffma2(acc[i][1], pa, vb0.y);
                ffma2(acc[i][2], pa, vb1.x);
                ffma2(acc[i][3], pa, vb1.y);
            }
        }
    }
    float bias[8];
    #pragma unroll
    for (int j = 0; j < 8; ++j) { int n = n0 + tx * 8 + j; bias[j] = bih[n] + bhh[n]; }
    #pragma unroll
    for (int i = 0; i < 8; ++i) {
        float2 c0v = unpack2(acc[i][0]), c1v = unpack2(acc[i][1]);
        float2 c2v = unpack2(acc[i][2]), c3v = unpack2(acc[i][3]);
        size_t o = (size_t)(m0 + ty * 8 + i) * G4 + n0 + tx * 8;
        float4 v0, v1;
        v0.x = c0v.x + bias[0]; v0.y = c0v.y + bias[1];
        v0.z = c1v.x + bias[2]; v0.w = c1v.y + bias[3];
        v1.x = c2v.x + bias[4]; v1.y = c2v.y + bias[5];
        v1.z = c3v.x + bias[6]; v1.w = c3v.y + bias[7];
        *(float4*)(g_xg + o) = v0; *(float4*)(g_xg + o + 4) = v1;
    }
}

// ===========================================================================
// Phase 2: persistent rec kernel, fp16 mma.sync 2-term (W fp16, h = hi+lo fp16).
// CTA r owns 8 hidden units -> D[32 gate rows x 32 batch], K=1024.
// Whole h staged single-buffered each step; warp = (ksc 0..3, nh 0..1, mh 0..1)
// -> m16 x n16 x K256. Two syncthreads per step.
// ===========================================================================
#define WP 1032                      // padded row, fp16 elems (2064 B)
#define OFF_W    0                                 // W   [32][WP] fp16 : 66048 B
#define OFF_HHI  (32 * WP * 2)                     // Hhi [32][WP] fp16 : 66048 B
#define OFF_HLO  (2 * 32 * WP * 2)                 // Hlo [32][WP] fp16 : 66048 B
#define OFF_PSM  (3 * 32 * WP * 2)                 // psm [4][32][33] f32: 16896 B
#define OFF_CSM  (OFF_PSM + 4 * 32 * 33 * 4)       // csm [8][33] f32   : 1056 B
#define SMEM_REC (OFF_CSM + 8 * 33 * 4)            // 216096 B

__global__ __launch_bounds__(NT, 1) void lstm_rec_kernel(
    const float* __restrict__ Whh, const float* __restrict__ h0,
    const float* __restrict__ c0, float* __restrict__ out)
{
    extern __shared__ __align__(16) char sm[];
    const u32 smb = smem_u32(sm);
    const int tid = threadIdx.x, lane = tid & 31, wid = tid >> 5;
    const int r = blockIdx.x, j0 = r * 8;

    u16* Wsm = (u16*)(sm + OFF_W);
    float* psm = (float*)(sm + OFF_PSM);     // [4][32][33]
    float* csm = (float*)(sm + OFF_CSM);     // [8][33]

    // ---- one-time: W_hh slice -> fp16 in SMEM (gate-major rows rr=q*8+jj) ----
    for (int idx = tid; idx < 32 * 1024; idx += NT) {
        int rr = idx >> 10, k = idx & 1023;
        int q = rr >> 3, jj = rr & 7;
        float w = Whh[(size_t)(q * HID_ + j0 + jj) * HID_ + k];
        Wsm[rr * WP + k] = __half_as_ushort(__float2half_rn(w));
    }

    // ---- cell state + h0 publish (threads < 256) ----
    const int b = tid >> 3, jj = tid & 7;
    if (tid < 256) {
        csm[jj * 33 + b] = c0[(size_t)b * HID_ + j0 + jj];
        float v = h0[(size_t)b * HID_ + j0 + jj];
        __half hi = __float2half_rn(v);
        __half lo = __float2half_rn(v - __half2float(hi));
        g_hhi[b * HID_ + j0 + jj] = __half_as_ushort(hi);
        g_hlo[b * HID_ + j0 + jj] = __half_as_ushort(lo);
    }
    grid_barrier_tree(r);

    // ---- warp mapping: ksc (K-slice of 256), nh (batch half), mh (row half) ----
    const int ksc = wid & 3, nh = (wid >> 2) & 1, mh = wid >> 3;
    const u32 aOff = smb + OFF_W +
        ((u32)((mh * 16 + (lane & 15)) * WP + ksc * 256 + (lane >> 4) * 8)) * 2;
    const u32 bRow = (u32)((nh * 16 + (lane >> 4) * 8 + (lane & 7)) * WP
                           + ksc * 256 + ((lane >> 3) & 1) * 8) * 2;
    const u32 bHiOff = smb + OFF_HHI + bRow;
    const u32 bLoOff = smb + OFF_HLO + bRow;

    for (int t = 0; t < T_; ++t) {
        // xg prefetch (threads < 256)
        float xgi, xgf, xgg, xgo;
        if (tid < 256) {
            const size_t xb = (((size_t)b * T_ + t) << 12) + j0 + jj;
            xgi = __ldcg(g_xg + xb);
            xgf = __ldcg(g_xg + xb + 1024);
            xgg = __ldcg(g_xg + xb + 2048);
            xgo = __ldcg(g_xg + xb + 3072);
        }

        // stage WHOLE h (hi+lo) single-buffered: 16 x uint4 per thread
        {
            u16* dhi = (u16*)(sm + OFF_HHI);
            u16* dlo = (u16*)(sm + OFF_HLO);
            #pragma unroll
            for (int i = 0; i < 8; ++i) {
                u32 u = (u32)(i * NT + tid);          // 0..4095
                u32 row = u >> 7, seg = (u & 127) * 8;
                *(uint4*)(dhi + row * WP + seg) =
                    __ldcg((const uint4*)(g_hhi + row * HID_ + seg));
                *(uint4*)(dlo + row * WP + seg) =
                    __ldcg((const uint4*)(g_hlo + row * HID_ + seg));
            }
        }
        __syncthreads();

        // MMA: 16 ktiles, no intervening syncs
        float D[2][4];
        #pragma unroll
        for (int n = 0; n < 2; ++n)
            #pragma unroll
            for (int i = 0; i < 4; ++i) D[n][i] = 0.f;

        u32 aA = aOff, bH = bHiOff, bL = bLoOff;
        #pragma unroll
        for (int kt = 0; kt < 16; ++kt) {
            u32 a0, a1, a2, a3, h0r, h1r, h2r, h3r, l0r, l1r, l2r, l3r;
            ldsm_x4(a0, a1, a2, a3, aA);
            ldsm_x4(h0r, h1r, h2r, h3r, bH);
            ldsm_x4(l0r, l1r, l2r, l3r, bL);
            mma_f16(D[0][0], D[0][1], D[0][2], D[0][3], a0, a1, a2, a3, h0r, h1r);
            mma_f16(D[1][0], D[1][1], D[1][2], D[1][3], a0, a1, a2, a3, h2r, h3r);
            mma_f16(D[0][0], D[0][1], D[0][2], D[0][3], a0, a1, a2, a3, l0r, l1r);
            mma_f16(D[1][0], D[1][1], D[1][2], D[1][3], a0, a1, a2, a3, l2r, l3r);
            aA += 32; bH += 32; bL += 32;
        }

        // K-partial D -> psm[ksc]
        {
            const int row = mh * 16 + (lane >> 2);
            const int col = nh * 16 + (lane & 3) * 2;
            float* pr = psm + (ksc * 32 + row) * 33;
            #pragma unroll
            for (int n = 0; n < 2; ++n) {
                pr[col + n * 8]              = D[n][0];
                pr[col + n * 8 + 1]          = D[n][1];
                pr[8 * 33 + col + n * 8]     = D[n][2];
                pr[8 * 33 + col + n * 8 + 1] = D[n][3];
            }
        }
        __syncthreads();

        // cell update (threads < 256): sum 4 K-partials per gate
        if (tid < 256) {
            float gi = 0.f, gf = 0.f, gg = 0.f, go = 0.f;
            #pragma unroll
            for (int s = 0; s < 4; ++s) {
                const float* ps = psm + s * 32 * 33;
                gi += ps[(jj)      * 33 + b];
                gf += ps[(8  + jj) * 33 + b];
                gg += ps[(16 + jj) * 33 + b];
                go += ps[(24 + jj) * 33 + b];
            }
            float pi = gi + xgi, pf = gf + xgf, pg = gg + xgg, po = go + xgo;
            float ig = 1.0f / (1.0f + expf(-pi));
            float fg = 1.0f / (1.0f + expf(-pf));
            float gt = tanhf(pg);
            float og = 1.0f / (1.0f + expf(-po));
            float cn = fmaf(fg, csm[jj * 33 + b], ig * gt);
            csm[jj * 33 + b] = cn;
            float hv = og * tanhf(cn);
            if (t == T_ - 1) {
                out[(size_t)b * HID_ + j0 + jj] = hv;
            } else {
                __half hi = __float2half_rn(hv);
                __half lo = __float2half_rn(hv - __half2float(hi));
                g_hhi[b * HID_ + j0 + jj] = __half_as_ushort(hi);
                g_hlo[b * HID_ + j0 + jj] = __half_as_ushort(lo);
            }
        }
        grid_barrier_tree(r);
    }
}

// ===========================================================================
// launch
// ===========================================================================
extern "C" void kernel_launch(void* const* d_in, const int* in_sizes, int n_in,
                              void* d_out, int out_size) {
    const float* x   = (const float*)d_in[0];
    const float* h0  = (const float*)d_in[1];
    const float* c0  = (const float*)d_in[2];
    const float* Wih = (const float*)d_in[3];
    const float* Whh = (const float*)d_in[4];
    const float* bih = (const float*)d_in[5];
    const float* bhh = (const float*)d_in[6];
    float* out = (float*)d_out;

    cudaFuncSetAttribute(lstm_rec_kernel,
                         cudaFuncAttributeMaxDynamicSharedMemorySize, SMEM_REC);

    dim3 grid(G4 / BN, (B_ * T_) / BM);
    xg_gemm_kernel<<<grid, 256>>>(x, Wih, bih, bhh);

    lstm_rec_kernel<<<NREC, NT, SMEM_REC>>>(Whh, h0, c0, out);
}

// round 17
// speedup vs baseline: 2.0202x; 1.1976x over previous
#include <cuda_runtime.h>
#include <cuda_fp16.h>
#include <math.h>
#include <stdint.h>

#define B_    32
#define T_    512
#define HID_  1024
#define G4    4096
#define NREC  128
#define NT    512          // threads per rec CTA (16 warps)

typedef unsigned int u32;
typedef unsigned long long ull;
typedef unsigned short u16;

// ===========================================================================
// Device scratch
// ===========================================================================
__device__ float g_xg[(size_t)B_ * T_ * G4];          // [B][T][4H] fp32
__device__ __align__(16) u16 g_hh[B_ * HID_];         // h fp16, [b][j]
__device__ u32 g_grp_cnt[16 * 32];                    // group counters, 128B apart
__device__ u32 g_root_cnt, g_root_gen;

// ===========================================================================
// helpers
// ===========================================================================
__device__ __forceinline__ u32 smem_u32(const void* p) {
    u32 a;
    asm("{ .reg .u64 t; cvta.to.shared.u64 t, %1; cvt.u32.u64 %0, t; }" : "=r"(a) : "l"(p));
    return a;
}
__device__ __forceinline__ void ldsm_x4(u32& r0, u32& r1, u32& r2, u32& r3, u32 addr) {
    asm volatile("ldmatrix.sync.aligned.m8n8.x4.shared.b16 {%0,%1,%2,%3}, [%4];"
                 : "=r"(r0), "=r"(r1), "=r"(r2), "=r"(r3) : "r"(addr));
}
__device__ __forceinline__ void mma_f16(float& d0, float& d1, float& d2, float& d3,
                                        u32 a0, u32 a1, u32 a2, u32 a3, u32 b0, u32 b1) {
    asm volatile("mma.sync.aligned.m16n8k16.row.col.f32.f16.f16.f32 "
                 "{%0,%1,%2,%3}, {%4,%5,%6,%7}, {%8,%9}, {%0,%1,%2,%3};"
                 : "+f"(d0), "+f"(d1), "+f"(d2), "+f"(d3)
                 : "r"(a0), "r"(a1), "r"(a2), "r"(a3), "r"(b0), "r"(b1));
}
// f32x2 (phase-1 GEMM)
__device__ __forceinline__ void ffma2(ull& d, ull a, ull b) {
    asm("fma.rn.f32x2 %0, %1, %2, %0;" : "+l"(d) : "l"(a), "l"(b));
}
__device__ __forceinline__ ull pack2(float x) {
    ull r; asm("mov.b64 %0, {%1, %1};" : "=l"(r) : "r"(__float_as_uint(x))); return r;
}
__device__ __forceinline__ float2 unpack2(ull v) {
    unsigned lo, hi; asm("mov.b64 {%0, %1}, %2;" : "=r"(lo), "=r"(hi) : "l"(v));
    return make_float2(__uint_as_float(lo), __uint_as_float(hi));
}

// Two-level grid barrier: 16 groups x 8 CTAs, self-resetting (replay-safe).
__device__ __forceinline__ void grid_barrier_tree(int r) {
    __syncthreads();
    if (threadIdx.x == 0) {
        volatile u32* vgen = &g_root_gen;
        u32 gen = *vgen;
        __threadfence();
        u32* gcnt = &g_grp_cnt[(r >> 3) * 32];
        if (atomicAdd(gcnt, 1u) == 7u) {
            *gcnt = 0u;
            __threadfence();
            if (atomicAdd(&g_root_cnt, 1u) == 15u) {
                g_root_cnt = 0u;
                __threadfence();
                *vgen = gen + 1u;
            } else {
                while (*vgen == gen) { }
            }
        } else {
            while (*vgen == gen) { }
        }
        __threadfence();
    }
    __syncthreads();
}

// ===========================================================================
// Phase 1: xg = x @ W_ih^T + (b_ih + b_hh).  FFMA2 SGEMM (verbatim, proven)
// ===========================================================================
#define BM 128
#define BN 128
#define BK 16
__global__ __launch_bounds__(256) void xg_gemm_kernel(
    const float* __restrict__ x, const float* __restrict__ Wih,
    const float* __restrict__ bih, const float* __restrict__ bhh)
{
    __shared__ __align__(16) float As[BK][BM + 4];
    __shared__ __align__(16) float Bs[BK][BN + 4];
    const int m0 = blockIdx.y * BM, n0 = blockIdx.x * BN;
    const int tid = threadIdx.x;
    const int tx = tid & 15, ty = tid >> 4;
    const int lrow = tid >> 2, lcol = (tid & 3) << 2;

    ull acc[8][4];
    #pragma unroll
    for (int i = 0; i < 8; ++i)
        #pragma unroll
        for (int j = 0; j < 4; ++j) acc[i][j] = 0ull;

    for (int kc = 0; kc < 1024; kc += BK) {
        float4 a0 = *(const float4*)(x   + (size_t)(m0 + lrow)      * 1024 + kc + lcol);
        float4 a1 = *(const float4*)(x   + (size_t)(m0 + lrow + 64) * 1024 + kc + lcol);
        float4 b0 = *(const float4*)(Wih + (size_t)(n0 + lrow)      * 1024 + kc + lcol);
        float4 b1 = *(const float4*)(Wih + (size_t)(n0 + lrow + 64) * 1024 + kc + lcol);
        __syncthreads();
        As[lcol + 0][lrow] = a0.x; As[lcol + 1][lrow] = a0.y;
        As[lcol + 2][lrow] = a0.z; As[lcol + 3][lrow] = a0.w;
        As[lcol + 0][lrow + 64] = a1.x; As[lcol + 1][lrow + 64] = a1.y;
        As[lcol + 2][lrow + 64] = a1.z; As[lcol + 3][lrow + 64] = a1.w;
        Bs[lcol + 0][lrow] = b0.x; Bs[lcol + 1][lrow] = b0.y;
        Bs[lcol + 2][lrow] = b0.z; Bs[lcol + 3][lrow] = b0.w;
        Bs[lcol + 0][lrow + 64] = b1.x; Bs[lcol + 1][lrow + 64] = b1.y;
        Bs[lcol + 2][lrow + 64] = b1.z; Bs[lcol + 3][lrow + 64] = b1.w;
        __syncthreads();
        #pragma unroll
        for (int k = 0; k < BK; ++k) {
            float4 va0 = *(const float4*)&As[k][ty * 8];
            float4 va1 = *(const float4*)&As[k][ty * 8 + 4];
            ulonglong2 vb0 = *(const ulonglong2*)&Bs[k][tx * 8];
            ulonglong2 vb1 = *(const ulonglong2*)&Bs[k][tx * 8 + 4];
            float ar[8] = {va0.x, va0.y, va0.z, va0.w, va1.x, va1.y, va1.z, va1.w};
            #pragma unroll
            for (int i = 0; i < 8; ++i) {
                ull pa = pack2(ar[i]);
                ffma2(acc[i][0], pa, vb0.x);
                ffma2(acc[i][1], pa, vb0.y);
                ffma2(acc[i][2], pa, vb1.x);
                ffma2(acc[i][3], pa, vb1.y);
            }
        }
    }
    float bias[8];
    #pragma unroll
    for (int j = 0; j < 8; ++j) { int n = n0 + tx * 8 + j; bias[j] = bih[n] + bhh[n]; }
    #pragma unroll
    for (int i = 0; i < 8; ++i) {
        float2 c0v = unpack2(acc[i][0]), c1v = unpack2(acc[i][1]);
        float2 c2v = unpack2(acc[i][2]), c3v = unpack2(acc[i][3]);
        size_t o = (size_t)(m0 + ty * 8 + i) * G4 + n0 + tx * 8;
        float4 v0, v1;
        v0.x = c0v.x + bias[0]; v0.y = c0v.y + bias[1];
        v0.z = c1v.x + bias[2]; v0.w = c1v.y + bias[3];
        v1.x = c2v.x + bias[4]; v1.y = c2v.y + bias[5];
        v1.z = c3v.x + bias[6]; v1.w = c3v.y + bias[7];
        *(float4*)(g_xg + o) = v0; *(float4*)(g_xg + o + 4) = v1;
    }
}

// ===========================================================================
// Phase 2: persistent rec kernel, fp16 mma.sync, W register-resident.
// CTA r owns 8 hidden units -> D[32 gate rows x 32 batch], K=1024.
// Warp = (ksc 0..3, nh 0..1, mh 0..1): m16 x n16 x K256.
// W frags loaded to registers ONCE; h (fp16, single) staged each step into
// the SMEM region that W occupied during init. Two syncthreads per step.
// ===========================================================================
#define WP 1032                                    // padded row, fp16 elems
#define OFF_H    0                                 // h [32][WP] fp16 : 66048 B (aliases W init)
#define OFF_PSM  (32 * WP * 2)                     // psm [4][32][33] f32 : 16896 B
#define OFF_CSM  (OFF_PSM + 4 * 32 * 33 * 4)       // csm [8][33] f32 : 1056 B
#define SMEM_REC (OFF_CSM + 8 * 33 * 4)            // 84000 B

__global__ __launch_bounds__(NT, 1) void lstm_rec_kernel(
    const float* __restrict__ Whh, const float* __restrict__ h0,
    const float* __restrict__ c0, float* __restrict__ out)
{
    extern __shared__ __align__(16) char sm[];
    const u32 smb = smem_u32(sm);
    const int tid = threadIdx.x, lane = tid & 31, wid = tid >> 5;
    const int r = blockIdx.x, j0 = r * 8;

    u16* Hsm = (u16*)(sm + OFF_H);           // also W staging during init
    float* psm = (float*)(sm + OFF_PSM);     // [4][32][33]
    float* csm = (float*)(sm + OFF_CSM);     // [8][33]

    // ---- warp mapping: ksc (K-slice of 256), nh (batch half), mh (row half) ----
    const int ksc = wid & 3, nh = (wid >> 2) & 1, mh = wid >> 3;

    // ---- init: W_hh slice -> fp16 SMEM (gate-major rows rr=q*8+jj) ----
    for (int idx = tid; idx < 32 * 1024; idx += NT) {
        int rr = idx >> 10, k = idx & 1023;
        int q = rr >> 3, jj = rr & 7;
        float w = Whh[(size_t)(q * HID_ + j0 + jj) * HID_ + k];
        Hsm[rr * WP + k] = __half_as_ushort(__float2half_rn(w));
    }
    __syncthreads();

    // ---- A (W) fragments -> registers, kept for all 512 steps ----
    u32 a[16][4];
    {
        u32 aA = smb + OFF_H +
            ((u32)((mh * 16 + (lane & 15)) * WP + ksc * 256 + (lane >> 4) * 8)) * 2;
        #pragma unroll
        for (int kt = 0; kt < 16; ++kt) {
            ldsm_x4(a[kt][0], a[kt][1], a[kt][2], a[kt][3], aA);
            aA += 32;
        }
    }

    // ---- cell state + h0 publish (threads < 256) ----
    const int b = tid >> 3, jj = tid & 7;
    if (tid < 256) {
        csm[jj * 33 + b] = c0[(size_t)b * HID_ + j0 + jj];
        float v = h0[(size_t)b * HID_ + j0 + jj];
        g_hh[b * HID_ + j0 + jj] = __half_as_ushort(__float2half_rn(v));
    }
    __syncthreads();          // all W ldsm done before Hsm is overwritten
    grid_barrier_tree(r);     // all h0 published

    // B ldsm base: batch = nh*16 + (lane>>4)*8 + (lane&7), k-seg ksc*256 + ((lane>>3)&1)*8
    const u32 bBase = smb + OFF_H +
        (u32)((nh * 16 + (lane >> 4) * 8 + (lane & 7)) * WP
              + ksc * 256 + ((lane >> 3) & 1) * 8) * 2;

    for (int t = 0; t < T_; ++t) {
        // xg prefetch (threads < 256)
        float xgi, xgf, xgg, xgo;
        if (tid < 256) {
            const size_t xb = (((size_t)b * T_ + t) << 12) + j0 + jj;
            xgi = __ldcg(g_xg + xb);
            xgf = __ldcg(g_xg + xb + 1024);
            xgg = __ldcg(g_xg + xb + 2048);
            xgo = __ldcg(g_xg + xb + 3072);
        }

        // stage whole h: 8 x uint4 per thread (64 KB total)
        #pragma unroll
        for (int i = 0; i < 8; ++i) {
            u32 u = (u32)(i * NT + tid);          // 0..4095
            u32 row = u >> 7, seg = (u & 127) * 8;
            *(uint4*)(Hsm + row * WP + seg) =
                __ldcg((const uint4*)(g_hh + row * HID_ + seg));
        }
        __syncthreads();

        // MMA: 16 ktiles, B-LDSM only, W from registers
        float D[2][4];
        #pragma unroll
        for (int n = 0; n < 2; ++n)
            #pragma unroll
            for (int i = 0; i < 4; ++i) D[n][i] = 0.f;

        u32 bA = bBase;
        #pragma unroll
        for (int kt = 0; kt < 16; ++kt) {
            u32 h0r, h1r, h2r, h3r;
            ldsm_x4(h0r, h1r, h2r, h3r, bA);
            mma_f16(D[0][0], D[0][1], D[0][2], D[0][3],
                    a[kt][0], a[kt][1], a[kt][2], a[kt][3], h0r, h1r);
            mma_f16(D[1][0], D[1][1], D[1][2], D[1][3],
                    a[kt][0], a[kt][1], a[kt][2], a[kt][3], h2r, h3r);
            bA += 32;
        }

        // K-partial D -> psm[ksc]
        {
            const int row = mh * 16 + (lane >> 2);
            const int col = nh * 16 + (lane & 3) * 2;
            float* pr = psm + (ksc * 32 + row) * 33;
            #pragma unroll
            for (int n = 0; n < 2; ++n) {
                pr[col + n * 8]              = D[n][0];
                pr[col + n * 8 + 1]          = D[n][1];
                pr[8 * 33 + col + n * 8]     = D[n][2];
                pr[8 * 33 + col + n * 8 + 1] = D[n][3];
            }
        }
        __syncthreads();

        // cell update (threads < 256): sum 4 K-partials per gate
        if (tid < 256) {
            float gi = 0.f, gf = 0.f, gg = 0.f, go = 0.f;
            #pragma unroll
            for (int s = 0; s < 4; ++s) {
                const float* ps = psm + s * 32 * 33;
                gi += ps[(jj)      * 33 + b];
                gf += ps[(8  + jj) * 33 + b];
                gg += ps[(16 + jj) * 33 + b];
                go += ps[(24 + jj) * 33 + b];
            }
            float pi = gi + xgi, pf = gf + xgf, pg = gg + xgg, po = go + xgo;
            float ig = 1.0f / (1.0f + expf(-pi));
            float fg = 1.0f / (1.0f + expf(-pf));
            float gt = tanhf(pg);
            float og = 1.0f / (1.0f + expf(-po));
            float cn = fmaf(fg, csm[jj * 33 + b], ig * gt);
            csm[jj * 33 + b] = cn;
            float hv = og * tanhf(cn);
            if (t == T_ - 1) {
                out[(size_t)b * HID_ + j0 + jj] = hv;
            } else {
                g_hh[b * HID_ + j0 + jj] = __half_as_ushort(__float2half_rn(hv));
            }
        }
        grid_barrier_tree(r);
    }
}

// ===========================================================================
// launch
// ===========================================================================
extern "C" void kernel_launch(void* const* d_in, const int* in_sizes, int n_in,
                              void* d_out, int out_size) {
    const float* x   = (const float*)d_in[0];
    const float* h0  = (const float*)d_in[1];
    const float* c0  = (const float*)d_in[2];
    const float* Wih = (const float*)d_in[3];
    const float* Whh = (const float*)d_in[4];
    const float* bih = (const float*)d_in[5];
    const float* bhh = (const float*)d_in[6];
    float* out = (float*)d_out;

    cudaFuncSetAttribute(lstm_rec_kernel,
                         cudaFuncAttributeMaxDynamicSharedMemorySize, SMEM_REC);

    dim3 grid(G4 / BN, (B_ * T_) / BM);
    xg_gemm_kernel<<<grid, 256>>>(x, Wih, bih, bhh);

    lstm_rec_kernel<<<NREC, NT, SMEM_REC>>>(Whh, h0, c0, out);
}